// round 1
// baseline (speedup 1.0000x reference)
#include <cuda_runtime.h>
#include <math.h>

#define BSZ   32768
#define OBS   1024
#define OUTD  256
#define KCB   512
#define HENCD 1024

#define LOG2PI_F 1.83787706640934534f

// ---------------- scratch (device globals; no allocation allowed) -------------
__device__ float g_cbT[OBS * KCB];          // codebook transposed [D, K]
__device__ float g_cnorm[KCB];
__device__ float g_xnorm[BSZ];
__device__ float g_h1[(size_t)BSZ * 512];
__device__ float g_h2[(size_t)BSZ * 1024];
__device__ float g_enc[(size_t)BSZ * 1024];
__device__ float g_dist[(size_t)BSZ * 512];
__device__ int   g_prop[BSZ];
__device__ float g_quant[(size_t)BSZ * 1024];
__device__ float g_d0[(size_t)BSZ * 1024];
__device__ float g_d1[(size_t)BSZ * 2048];
__device__ float g_d2[(size_t)BSZ * 2048];
__device__ float g_recon[(size_t)BSZ * 1024];
__device__ float g_cs[(size_t)BSZ * 1536];
__device__ float g_a1[(size_t)BSZ * 2048];
__device__ float g_a2[(size_t)BSZ * 2048];
__device__ float g_mu[(size_t)BSZ * 256];
__device__ float g_part[2048 * 2];
__device__ float g_total[1];

// ---------------- helpers ------------------------------------------------------
__device__ __forceinline__ float blockReduceSum(float v) {
    __shared__ float sh[32];
    int lane = threadIdx.x & 31, wid = threadIdx.x >> 5;
#pragma unroll
    for (int o = 16; o > 0; o >>= 1) v += __shfl_down_sync(0xffffffffu, v, o);
    if (lane == 0) sh[wid] = v;
    __syncthreads();
    int nw = blockDim.x >> 5;
    v = (threadIdx.x < nw) ? sh[threadIdx.x] : 0.f;
    if (wid == 0) {
#pragma unroll
        for (int o = 16; o > 0; o >>= 1) v += __shfl_down_sync(0xffffffffu, v, o);
    }
    __syncthreads();
    return v;  // valid on thread 0
}

// ---------------- SGEMM: C[M,N] = epi(A[M,K] @ B[K,N]) -------------------------
// EPI 0: acc + bias[n]
// EPI 1: tanh(acc + bias[n])
// EPI 2: rown[m] + bias[n] - 2*acc        (squared-distance epilogue)
#define BM 128
#define BN 128
#define BK 8

template <int EPI>
__global__ void __launch_bounds__(256)
sgemm_kernel(const float* __restrict__ A, const float* __restrict__ B,
             const float* __restrict__ bias, const float* __restrict__ rown,
             float* __restrict__ C, int M, int N, int K) {
    __shared__ float As[2][BK][BM];
    __shared__ float Bs[2][BK][BN];

    const int tid = threadIdx.x;
    const int tx = tid & 15;   // 0..15
    const int ty = tid >> 4;   // 0..15
    const int m0 = blockIdx.y * BM;
    const int n0 = blockIdx.x * BN;

    const int arow = tid >> 1;
    const int akq = (tid & 1) * 4;
    const float* Aptr = A + (size_t)(m0 + arow) * K + akq;

    const int brow = tid >> 5;          // 0..7
    const int bcol = (tid & 31) * 4;    // 0..124
    const float* Bptr = B + (size_t)brow * N + n0 + bcol;

    float acc[8][8];
#pragma unroll
    for (int i = 0; i < 8; i++)
#pragma unroll
        for (int j = 0; j < 8; j++) acc[i][j] = 0.f;

    const int nt = K / BK;

    float4 a4 = *(const float4*)(Aptr);
    float4 b4 = *(const float4*)(Bptr);
    As[0][akq + 0][arow] = a4.x; As[0][akq + 1][arow] = a4.y;
    As[0][akq + 2][arow] = a4.z; As[0][akq + 3][arow] = a4.w;
    *(float4*)&Bs[0][brow][bcol] = b4;
    __syncthreads();

    int cur = 0;
    for (int t = 0; t < nt; t++) {
        if (t + 1 < nt) {
            a4 = *(const float4*)(Aptr + (t + 1) * BK);
            b4 = *(const float4*)(Bptr + (size_t)(t + 1) * BK * N);
        }
#pragma unroll
        for (int kk = 0; kk < BK; kk++) {
            float4 a0 = *(const float4*)&As[cur][kk][ty * 4];
            float4 a1 = *(const float4*)&As[cur][kk][64 + ty * 4];
            float4 b0 = *(const float4*)&Bs[cur][kk][tx * 4];
            float4 b1 = *(const float4*)&Bs[cur][kk][64 + tx * 4];
            float ar[8] = {a0.x, a0.y, a0.z, a0.w, a1.x, a1.y, a1.z, a1.w};
            float br[8] = {b0.x, b0.y, b0.z, b0.w, b1.x, b1.y, b1.z, b1.w};
#pragma unroll
            for (int i = 0; i < 8; i++)
#pragma unroll
                for (int j = 0; j < 8; j++) acc[i][j] = fmaf(ar[i], br[j], acc[i][j]);
        }
        if (t + 1 < nt) {
            int nx = cur ^ 1;
            As[nx][akq + 0][arow] = a4.x; As[nx][akq + 1][arow] = a4.y;
            As[nx][akq + 2][arow] = a4.z; As[nx][akq + 3][arow] = a4.w;
            *(float4*)&Bs[nx][brow][bcol] = b4;
        }
        __syncthreads();
        cur ^= 1;
    }

#pragma unroll
    for (int i = 0; i < 8; i++) {
        int r = m0 + ((i < 4) ? (ty * 4 + i) : (64 + ty * 4 + (i - 4)));
        float rn = (EPI == 2) ? rown[r] : 0.f;
#pragma unroll
        for (int jh = 0; jh < 2; jh++) {
            int c = n0 + jh * 64 + tx * 4;
            float4 bv = *(const float4*)(bias + c);
            const float* ap = &acc[i][jh * 4];
            float4 v;
            if (EPI == 2) {
                v.x = rn + bv.x - 2.f * ap[0];
                v.y = rn + bv.y - 2.f * ap[1];
                v.z = rn + bv.z - 2.f * ap[2];
                v.w = rn + bv.w - 2.f * ap[3];
            } else {
                v.x = ap[0] + bv.x; v.y = ap[1] + bv.y;
                v.z = ap[2] + bv.z; v.w = ap[3] + bv.w;
                if (EPI == 1) {
                    v.x = tanhf(v.x); v.y = tanhf(v.y);
                    v.z = tanhf(v.z); v.w = tanhf(v.w);
                }
            }
            *(float4*)(C + (size_t)r * N + c) = v;
        }
    }
}

// ---------------- small kernels -------------------------------------------------
__global__ void prep_codebook_kernel(const float* __restrict__ cb) {
    int k = blockIdx.x;  // 0..KCB-1
    float s = 0.f;
    for (int d = threadIdx.x; d < OBS; d += blockDim.x) {
        float v = cb[(size_t)k * OBS + d];
        g_cbT[(size_t)d * KCB + k] = v;
        s += v * v;
    }
    s = blockReduceSum(s);
    if (threadIdx.x == 0) g_cnorm[k] = s;
}

__global__ void rownorm_kernel(const float* __restrict__ x, float* __restrict__ out, int D) {
    int b = blockIdx.x;
    const float* r = x + (size_t)b * D;
    float s = 0.f;
    for (int d = threadIdx.x; d < D; d += blockDim.x) {
        float v = r[d];
        s += v * v;
    }
    s = blockReduceSum(s);
    if (threadIdx.x == 0) out[b] = s;
}

__global__ void argmin_kernel(const float* __restrict__ dist, float* __restrict__ prop_out_f) {
    __shared__ float sv[256];
    __shared__ int si[256];
    int b = blockIdx.x;
    const float* r = dist + (size_t)b * KCB;
    float best = INFINITY;
    int bi = KCB;
    for (int k = threadIdx.x; k < KCB; k += 256) {
        float v = r[k];
        if (v < best) { best = v; bi = k; }
    }
    sv[threadIdx.x] = best;
    si[threadIdx.x] = bi;
    __syncthreads();
    for (int s = 128; s > 0; s >>= 1) {
        if (threadIdx.x < s) {
            float ov = sv[threadIdx.x + s];
            int oi = si[threadIdx.x + s];
            if (ov < sv[threadIdx.x] || (ov == sv[threadIdx.x] && oi < si[threadIdx.x])) {
                sv[threadIdx.x] = ov;
                si[threadIdx.x] = oi;
            }
        }
        __syncthreads();
    }
    if (threadIdx.x == 0) {
        g_prop[b] = si[0];
        prop_out_f[b] = (float)si[0];
    }
}

__global__ void gather_kernel(const float* __restrict__ cb) {
    size_t i = (size_t)blockIdx.x * blockDim.x + threadIdx.x;  // B*OBS threads
    int b = (int)(i >> 10);
    int d = (int)(i & 1023);
    g_quant[i] = cb[(size_t)g_prop[b] * OBS + d];
}

__global__ void concat_kernel(const float* __restrict__ X) {
    size_t i = (size_t)blockIdx.x * blockDim.x + threadIdx.x;  // B*1536 threads
    int b = (int)(i / 1536);
    int j = (int)(i % 1536);
    g_cs[i] = (j < OBS) ? X[(size_t)b * OBS + j] : g_dist[(size_t)b * KCB + (j - OBS)];
}

__global__ void loss_partial_kernel(const float* __restrict__ dx) {
    const size_t NTOT = (size_t)BSZ * OBS;
    float s1 = 0.f, s2 = 0.f;
    for (size_t i = (size_t)blockIdx.x * blockDim.x + threadIdx.x; i < NTOT;
         i += (size_t)gridDim.x * blockDim.x) {
        float a = dx[i] - g_recon[i];
        s1 += a * a;
        float c = g_enc[i] - g_quant[i];
        s2 += c * c;
    }
    s1 = blockReduceSum(s1);
    __syncthreads();
    s2 = blockReduceSum(s2);
    if (threadIdx.x == 0) {
        g_part[2 * blockIdx.x + 0] = s1;
        g_part[2 * blockIdx.x + 1] = s2;
    }
}

__global__ void finalize_total_kernel(int nb, float* __restrict__ out_total) {
    float s1 = 0.f, s2 = 0.f;
    for (int i = threadIdx.x; i < nb; i += 256) {
        s1 += g_part[2 * i + 0];
        s2 += g_part[2 * i + 1];
    }
    s1 = blockReduceSum(s1);
    __syncthreads();
    s2 = blockReduceSum(s2);
    if (threadIdx.x == 0) {
        const float inv = 1.f / ((float)BSZ * (float)OBS);
        float tot = s1 * inv + 2.f * (s2 * inv);  // recon + vq + commit (KL_BETA=1)
        g_total[0] = tot;
        out_total[0] = tot;
    }
}

__global__ void policy_kernel(const float* __restrict__ A_, const float* __restrict__ log_std,
                              float* __restrict__ out_loss, float* __restrict__ out_losspi) {
    int b = blockIdx.x;
    int j = threadIdx.x;  // 256 threads == OUTD
    float ls = log_std[j];
    float sd = expf(ls);
    float z = (A_[(size_t)b * OUTD + j] - g_mu[(size_t)b * OUTD + j]) / sd;
    float logp = -0.5f * z * z - ls - 0.5f * LOG2PI_F;
    float term = 1.f / (expf(logp) + 0.1f);
    float lp = blockReduceSum(term);
    if (threadIdx.x == 0) {
        out_losspi[b] = lp;
        out_loss[b] = lp * g_total[0];
    }
}

// ---------------- launch -------------------------------------------------------
static inline dim3 gemm_grid(int M, int N) { return dim3(N / BN, M / BM); }

extern "C" void kernel_launch(void* const* d_in, const int* in_sizes, int n_in,
                              void* d_out, int out_size) {
    const float* X        = (const float*)d_in[0];
    const float* Delta_X  = (const float*)d_in[1];
    const float* A        = (const float*)d_in[2];
    const float* enc_w1   = (const float*)d_in[3];
    const float* enc_b1   = (const float*)d_in[4];
    const float* enc_w2   = (const float*)d_in[5];
    const float* enc_b2   = (const float*)d_in[6];
    const float* prenet_w = (const float*)d_in[7];
    const float* prenet_b = (const float*)d_in[8];
    const float* codebook = (const float*)d_in[9];
    const float* postnet_w= (const float*)d_in[10];
    const float* postnet_b= (const float*)d_in[11];
    const float* dec_w1   = (const float*)d_in[12];
    const float* dec_b1   = (const float*)d_in[13];
    const float* dec_w2   = (const float*)d_in[14];
    const float* dec_b2   = (const float*)d_in[15];
    const float* dec_w3   = (const float*)d_in[16];
    const float* dec_b3   = (const float*)d_in[17];
    const float* act_w1   = (const float*)d_in[18];
    const float* act_b1   = (const float*)d_in[19];
    const float* act_w2   = (const float*)d_in[20];
    const float* act_b2   = (const float*)d_in[21];
    const float* act_w3   = (const float*)d_in[22];
    const float* act_b3   = (const float*)d_in[23];
    const float* log_std  = (const float*)d_in[24];

    float* out = (float*)d_out;
    float* out_loss   = out;                       // [B]
    float* out_losspi = out + BSZ;                 // [B]
    float* out_X      = out + 2 * (size_t)BSZ;     // [B, OBS]
    float* out_prop   = out + 2 * (size_t)BSZ + (size_t)BSZ * OBS;  // [B]
    float* out_total  = out_prop + BSZ;            // [1]

    float *p_h1, *p_h2, *p_enc, *p_dist, *p_quant, *p_d0, *p_d1, *p_d2, *p_recon,
          *p_cs, *p_a1, *p_a2, *p_mu, *p_cbT, *p_cnorm, *p_xnorm;
    cudaGetSymbolAddress((void**)&p_h1, g_h1);
    cudaGetSymbolAddress((void**)&p_h2, g_h2);
    cudaGetSymbolAddress((void**)&p_enc, g_enc);
    cudaGetSymbolAddress((void**)&p_dist, g_dist);
    cudaGetSymbolAddress((void**)&p_quant, g_quant);
    cudaGetSymbolAddress((void**)&p_d0, g_d0);
    cudaGetSymbolAddress((void**)&p_d1, g_d1);
    cudaGetSymbolAddress((void**)&p_d2, g_d2);
    cudaGetSymbolAddress((void**)&p_recon, g_recon);
    cudaGetSymbolAddress((void**)&p_cs, g_cs);
    cudaGetSymbolAddress((void**)&p_a1, g_a1);
    cudaGetSymbolAddress((void**)&p_a2, g_a2);
    cudaGetSymbolAddress((void**)&p_mu, g_mu);
    cudaGetSymbolAddress((void**)&p_cbT, g_cbT);
    cudaGetSymbolAddress((void**)&p_cnorm, g_cnorm);
    cudaGetSymbolAddress((void**)&p_xnorm, g_xnorm);

    // 0. codebook transpose + norms
    prep_codebook_kernel<<<KCB, 256>>>(codebook);

    // 1-3. VQ encoder
    sgemm_kernel<1><<<gemm_grid(BSZ, 512), 256>>>(Delta_X, enc_w1, enc_b1, nullptr, p_h1, BSZ, 512, 1024);
    sgemm_kernel<1><<<gemm_grid(BSZ, 1024), 256>>>(p_h1, enc_w2, enc_b2, nullptr, p_h2, BSZ, 1024, 512);
    sgemm_kernel<0><<<gemm_grid(BSZ, 1024), 256>>>(p_h2, prenet_w, prenet_b, nullptr, p_enc, BSZ, 1024, 1024);

    // 4-6. distances + argmin + gather
    rownorm_kernel<<<BSZ, 256>>>(p_enc, p_xnorm, OBS);
    sgemm_kernel<2><<<gemm_grid(BSZ, KCB), 256>>>(p_enc, p_cbT, p_cnorm, p_xnorm, p_dist, BSZ, KCB, OBS);
    argmin_kernel<<<BSZ, 256>>>(p_dist, out_prop);
    gather_kernel<<<(BSZ * OBS) / 256, 256>>>(codebook);

    // 7-10. postnet + decoder (forward st_q == quantized)
    sgemm_kernel<1><<<gemm_grid(BSZ, HENCD), 256>>>(p_quant, postnet_w, postnet_b, nullptr, p_d0, BSZ, HENCD, 1024);
    sgemm_kernel<1><<<gemm_grid(BSZ, 2048), 256>>>(p_d0, dec_w1, dec_b1, nullptr, p_d1, BSZ, 2048, 1024);
    sgemm_kernel<1><<<gemm_grid(BSZ, 2048), 256>>>(p_d1, dec_w2, dec_b2, nullptr, p_d2, BSZ, 2048, 2048);
    sgemm_kernel<0><<<gemm_grid(BSZ, 1024), 256>>>(p_d2, dec_w3, dec_b3, nullptr, p_recon, BSZ, 1024, 2048);

    // 11-14. actor
    concat_kernel<<<((size_t)BSZ * 1536) / 256, 256>>>(X);
    sgemm_kernel<1><<<gemm_grid(BSZ, 2048), 256>>>(p_cs, act_w1, act_b1, nullptr, p_a1, BSZ, 2048, 1536);
    sgemm_kernel<1><<<gemm_grid(BSZ, 2048), 256>>>(p_a1, act_w2, act_b2, nullptr, p_a2, BSZ, 2048, 2048);
    sgemm_kernel<0><<<gemm_grid(BSZ, 256), 256>>>(p_a2, act_w3, act_b3, nullptr, p_mu, BSZ, 256, 2048);

    // 15-17. losses
    loss_partial_kernel<<<2048, 256>>>(Delta_X);
    finalize_total_kernel<<<1, 256>>>(2048, out_total);
    policy_kernel<<<BSZ, 256>>>(A, log_std, out_loss, out_losspi);

    // 18. X pass-through
    cudaMemcpyAsync(out_X, X, (size_t)BSZ * OBS * sizeof(float),
                    cudaMemcpyDeviceToDevice);
}

// round 2
// speedup vs baseline: 1.0544x; 1.0544x over previous
#include <cuda_runtime.h>
#include <math.h>

#define BSZ   32768
#define OBS   1024
#define OUTD  256
#define KCB   512
#define HENCD 1024

#define LOG2PI_F 1.83787706640934534f

// ---------------- scratch (device globals; no allocation allowed) -------------
__device__ float g_cbT[OBS * KCB];          // codebook transposed [D, K]
__device__ float g_cnorm[KCB];
__device__ float g_xnorm[BSZ];
__device__ float g_h1[(size_t)BSZ * 512];
__device__ float g_h2[(size_t)BSZ * 1024];
__device__ float g_enc[(size_t)BSZ * 1024];
__device__ float g_dist[(size_t)BSZ * 512];
__device__ int   g_prop[BSZ];
__device__ float g_quant[(size_t)BSZ * 1024];
__device__ float g_d0[(size_t)BSZ * 1024];
__device__ float g_d1[(size_t)BSZ * 2048];
__device__ float g_d2[(size_t)BSZ * 2048];
__device__ float g_recon[(size_t)BSZ * 1024];
__device__ float g_cs[(size_t)BSZ * 1536];
__device__ float g_a1[(size_t)BSZ * 2048];
__device__ float g_a2[(size_t)BSZ * 2048];
__device__ float g_mu[(size_t)BSZ * 256];
__device__ float g_part[2048 * 2];
__device__ float g_total[1];

// ---------------- packed f32x2 helpers (Blackwell FFMA2 path) ------------------
__device__ __forceinline__ unsigned long long pack2_bcast(float x) {
    unsigned long long r;
    asm("mov.b64 %0, {%1, %1};" : "=l"(r) : "f"(x));
    return r;
}
__device__ __forceinline__ void ffma2(unsigned long long& d, unsigned long long a,
                                      unsigned long long b) {
    asm("fma.rn.f32x2 %0, %1, %2, %0;" : "+l"(d) : "l"(a), "l"(b));
}
__device__ __forceinline__ float2 unpack2(unsigned long long v) {
    float2 f;
    asm("mov.b64 {%0, %1}, %2;" : "=f"(f.x), "=f"(f.y) : "l"(v));
    return f;
}

// ---------------- helpers ------------------------------------------------------
__device__ __forceinline__ float blockReduceSum(float v) {
    __shared__ float sh[32];
    int lane = threadIdx.x & 31, wid = threadIdx.x >> 5;
#pragma unroll
    for (int o = 16; o > 0; o >>= 1) v += __shfl_down_sync(0xffffffffu, v, o);
    if (lane == 0) sh[wid] = v;
    __syncthreads();
    int nw = blockDim.x >> 5;
    v = (threadIdx.x < nw) ? sh[threadIdx.x] : 0.f;
    if (wid == 0) {
#pragma unroll
        for (int o = 16; o > 0; o >>= 1) v += __shfl_down_sync(0xffffffffu, v, o);
    }
    __syncthreads();
    return v;  // valid on thread 0
}

// ---------------- SGEMM: C[M,N] = epi(A[M,K] @ B[K,N]) -------------------------
// EPI 0: acc + bias[n]
// EPI 1: tanh(acc + bias[n])
// EPI 2: rown[m] + bias[n] - 2*acc        (squared-distance epilogue)
#define BM 128
#define BN 128
#define BK 8

template <int EPI>
__global__ void __launch_bounds__(256)
sgemm_kernel(const float* __restrict__ A, const float* __restrict__ B,
             const float* __restrict__ bias, const float* __restrict__ rown,
             float* __restrict__ C, int M, int N, int K) {
    __shared__ __align__(16) float As[2][BK][BM];
    __shared__ __align__(16) float Bs[2][BK][BN];

    const int tid = threadIdx.x;
    const int tx = tid & 15;   // 0..15
    const int ty = tid >> 4;   // 0..15
    const int m0 = blockIdx.y * BM;
    const int n0 = blockIdx.x * BN;

    const int arow = tid >> 1;
    const int akq = (tid & 1) * 4;
    const float* Aptr = A + (size_t)(m0 + arow) * K + akq;

    const int brow = tid >> 5;          // 0..7
    const int bcol = (tid & 31) * 4;    // 0..124
    const float* Bptr = B + (size_t)brow * N + n0 + bcol;

    // accumulators: 8 rows x 4 packed column-pairs (64 fp32 lanes)
    unsigned long long acc2[8][4];
#pragma unroll
    for (int i = 0; i < 8; i++)
#pragma unroll
        for (int j = 0; j < 4; j++) acc2[i][j] = 0ull;

    const int nt = K / BK;

    float4 a4 = *(const float4*)(Aptr);
    float4 b4 = *(const float4*)(Bptr);
    As[0][akq + 0][arow] = a4.x; As[0][akq + 1][arow] = a4.y;
    As[0][akq + 2][arow] = a4.z; As[0][akq + 3][arow] = a4.w;
    *(float4*)&Bs[0][brow][bcol] = b4;
    __syncthreads();

    int cur = 0;
    for (int t = 0; t < nt; t++) {
        if (t + 1 < nt) {
            a4 = *(const float4*)(Aptr + (t + 1) * BK);
            b4 = *(const float4*)(Bptr + (size_t)(t + 1) * BK * N);
        }
#pragma unroll
        for (int kk = 0; kk < BK; kk++) {
            float4 a0 = *(const float4*)&As[cur][kk][ty * 4];
            float4 a1 = *(const float4*)&As[cur][kk][64 + ty * 4];
            // B pairs come out of LDS.128 already packed as register pairs
            ulonglong2 bq0 = *(const ulonglong2*)&Bs[cur][kk][tx * 4];
            ulonglong2 bq1 = *(const ulonglong2*)&Bs[cur][kk][64 + tx * 4];
            unsigned long long bb[4] = {bq0.x, bq0.y, bq1.x, bq1.y};
            float ar[8] = {a0.x, a0.y, a0.z, a0.w, a1.x, a1.y, a1.z, a1.w};
#pragma unroll
            for (int i = 0; i < 8; i++) {
                unsigned long long aa = pack2_bcast(ar[i]);
#pragma unroll
                for (int j = 0; j < 4; j++) ffma2(acc2[i][j], aa, bb[j]);
            }
        }
        if (t + 1 < nt) {
            int nx = cur ^ 1;
            As[nx][akq + 0][arow] = a4.x; As[nx][akq + 1][arow] = a4.y;
            As[nx][akq + 2][arow] = a4.z; As[nx][akq + 3][arow] = a4.w;
            *(float4*)&Bs[nx][brow][bcol] = b4;
        }
        __syncthreads();
        cur ^= 1;
    }

#pragma unroll
    for (int i = 0; i < 8; i++) {
        int r = m0 + ((i < 4) ? (ty * 4 + i) : (64 + ty * 4 + (i - 4)));
        float rn = (EPI == 2) ? rown[r] : 0.f;
#pragma unroll
        for (int jh = 0; jh < 2; jh++) {
            int c = n0 + jh * 64 + tx * 4;
            float4 bv = *(const float4*)(bias + c);
            float2 p0 = unpack2(acc2[i][jh * 2 + 0]);
            float2 p1 = unpack2(acc2[i][jh * 2 + 1]);
            float ap[4] = {p0.x, p0.y, p1.x, p1.y};
            float4 v;
            if (EPI == 2) {
                v.x = rn + bv.x - 2.f * ap[0];
                v.y = rn + bv.y - 2.f * ap[1];
                v.z = rn + bv.z - 2.f * ap[2];
                v.w = rn + bv.w - 2.f * ap[3];
            } else {
                v.x = ap[0] + bv.x; v.y = ap[1] + bv.y;
                v.z = ap[2] + bv.z; v.w = ap[3] + bv.w;
                if (EPI == 1) {
                    v.x = tanhf(v.x); v.y = tanhf(v.y);
                    v.z = tanhf(v.z); v.w = tanhf(v.w);
                }
            }
            *(float4*)(C + (size_t)r * N + c) = v;
        }
    }
}

// ---------------- small kernels -------------------------------------------------
__global__ void prep_codebook_kernel(const float* __restrict__ cb) {
    int k = blockIdx.x;  // 0..KCB-1
    float s = 0.f;
    for (int d = threadIdx.x; d < OBS; d += blockDim.x) {
        float v = cb[(size_t)k * OBS + d];
        g_cbT[(size_t)d * KCB + k] = v;
        s += v * v;
    }
    s = blockReduceSum(s);
    if (threadIdx.x == 0) g_cnorm[k] = s;
}

__global__ void rownorm_kernel(const float* __restrict__ x, float* __restrict__ out, int D) {
    int b = blockIdx.x;
    const float* r = x + (size_t)b * D;
    float s = 0.f;
    for (int d = threadIdx.x; d < D; d += blockDim.x) {
        float v = r[d];
        s += v * v;
    }
    s = blockReduceSum(s);
    if (threadIdx.x == 0) out[b] = s;
}

__global__ void argmin_kernel(const float* __restrict__ dist, float* __restrict__ prop_out_f) {
    __shared__ float sv[256];
    __shared__ int si[256];
    int b = blockIdx.x;
    const float* r = dist + (size_t)b * KCB;
    float best = INFINITY;
    int bi = KCB;
    for (int k = threadIdx.x; k < KCB; k += 256) {
        float v = r[k];
        if (v < best) { best = v; bi = k; }
    }
    sv[threadIdx.x] = best;
    si[threadIdx.x] = bi;
    __syncthreads();
    for (int s = 128; s > 0; s >>= 1) {
        if (threadIdx.x < s) {
            float ov = sv[threadIdx.x + s];
            int oi = si[threadIdx.x + s];
            if (ov < sv[threadIdx.x] || (ov == sv[threadIdx.x] && oi < si[threadIdx.x])) {
                sv[threadIdx.x] = ov;
                si[threadIdx.x] = oi;
            }
        }
        __syncthreads();
    }
    if (threadIdx.x == 0) {
        g_prop[b] = si[0];
        prop_out_f[b] = (float)si[0];
    }
}

__global__ void gather_kernel(const float* __restrict__ cb) {
    size_t i = (size_t)blockIdx.x * blockDim.x + threadIdx.x;  // B*OBS threads
    int b = (int)(i >> 10);
    int d = (int)(i & 1023);
    g_quant[i] = cb[(size_t)g_prop[b] * OBS + d];
}

__global__ void concat_kernel(const float* __restrict__ X) {
    size_t i = (size_t)blockIdx.x * blockDim.x + threadIdx.x;  // B*1536 threads
    int b = (int)(i / 1536);
    int j = (int)(i % 1536);
    g_cs[i] = (j < OBS) ? X[(size_t)b * OBS + j] : g_dist[(size_t)b * KCB + (j - OBS)];
}

__global__ void loss_partial_kernel(const float* __restrict__ dx) {
    const size_t NTOT = (size_t)BSZ * OBS;
    float s1 = 0.f, s2 = 0.f;
    for (size_t i = (size_t)blockIdx.x * blockDim.x + threadIdx.x; i < NTOT;
         i += (size_t)gridDim.x * blockDim.x) {
        float a = dx[i] - g_recon[i];
        s1 += a * a;
        float c = g_enc[i] - g_quant[i];
        s2 += c * c;
    }
    s1 = blockReduceSum(s1);
    __syncthreads();
    s2 = blockReduceSum(s2);
    if (threadIdx.x == 0) {
        g_part[2 * blockIdx.x + 0] = s1;
        g_part[2 * blockIdx.x + 1] = s2;
    }
}

__global__ void finalize_total_kernel(int nb, float* __restrict__ out_total) {
    float s1 = 0.f, s2 = 0.f;
    for (int i = threadIdx.x; i < nb; i += 256) {
        s1 += g_part[2 * i + 0];
        s2 += g_part[2 * i + 1];
    }
    s1 = blockReduceSum(s1);
    __syncthreads();
    s2 = blockReduceSum(s2);
    if (threadIdx.x == 0) {
        const float inv = 1.f / ((float)BSZ * (float)OBS);
        float tot = s1 * inv + 2.f * (s2 * inv);  // recon + vq + commit (KL_BETA=1)
        g_total[0] = tot;
        out_total[0] = tot;
    }
}

__global__ void policy_kernel(const float* __restrict__ A_, const float* __restrict__ log_std,
                              float* __restrict__ out_loss, float* __restrict__ out_losspi) {
    int b = blockIdx.x;
    int j = threadIdx.x;  // 256 threads == OUTD
    float ls = log_std[j];
    float sd = expf(ls);
    float z = (A_[(size_t)b * OUTD + j] - g_mu[(size_t)b * OUTD + j]) / sd;
    float logp = -0.5f * z * z - ls - 0.5f * LOG2PI_F;
    float term = 1.f / (expf(logp) + 0.1f);
    float lp = blockReduceSum(term);
    if (threadIdx.x == 0) {
        out_losspi[b] = lp;
        out_loss[b] = lp * g_total[0];
    }
}

// ---------------- launch -------------------------------------------------------
static inline dim3 gemm_grid(int M, int N) { return dim3(N / BN, M / BM); }

extern "C" void kernel_launch(void* const* d_in, const int* in_sizes, int n_in,
                              void* d_out, int out_size) {
    const float* X        = (const float*)d_in[0];
    const float* Delta_X  = (const float*)d_in[1];
    const float* A        = (const float*)d_in[2];
    const float* enc_w1   = (const float*)d_in[3];
    const float* enc_b1   = (const float*)d_in[4];
    const float* enc_w2   = (const float*)d_in[5];
    const float* enc_b2   = (const float*)d_in[6];
    const float* prenet_w = (const float*)d_in[7];
    const float* prenet_b = (const float*)d_in[8];
    const float* codebook = (const float*)d_in[9];
    const float* postnet_w= (const float*)d_in[10];
    const float* postnet_b= (const float*)d_in[11];
    const float* dec_w1   = (const float*)d_in[12];
    const float* dec_b1   = (const float*)d_in[13];
    const float* dec_w2   = (const float*)d_in[14];
    const float* dec_b2   = (const float*)d_in[15];
    const float* dec_w3   = (const float*)d_in[16];
    const float* dec_b3   = (const float*)d_in[17];
    const float* act_w1   = (const float*)d_in[18];
    const float* act_b1   = (const float*)d_in[19];
    const float* act_w2   = (const float*)d_in[20];
    const float* act_b2   = (const float*)d_in[21];
    const float* act_w3   = (const float*)d_in[22];
    const float* act_b3   = (const float*)d_in[23];
    const float* log_std  = (const float*)d_in[24];

    float* out = (float*)d_out;
    float* out_loss   = out;                       // [B]
    float* out_losspi = out + BSZ;                 // [B]
    float* out_X      = out + 2 * (size_t)BSZ;     // [B, OBS]
    float* out_prop   = out + 2 * (size_t)BSZ + (size_t)BSZ * OBS;  // [B]
    float* out_total  = out_prop + BSZ;            // [1]

    float *p_h1, *p_h2, *p_enc, *p_dist, *p_quant, *p_d0, *p_d1, *p_d2, *p_recon,
          *p_cs, *p_a1, *p_a2, *p_mu, *p_cbT, *p_cnorm, *p_xnorm;
    cudaGetSymbolAddress((void**)&p_h1, g_h1);
    cudaGetSymbolAddress((void**)&p_h2, g_h2);
    cudaGetSymbolAddress((void**)&p_enc, g_enc);
    cudaGetSymbolAddress((void**)&p_dist, g_dist);
    cudaGetSymbolAddress((void**)&p_quant, g_quant);
    cudaGetSymbolAddress((void**)&p_d0, g_d0);
    cudaGetSymbolAddress((void**)&p_d1, g_d1);
    cudaGetSymbolAddress((void**)&p_d2, g_d2);
    cudaGetSymbolAddress((void**)&p_recon, g_recon);
    cudaGetSymbolAddress((void**)&p_cs, g_cs);
    cudaGetSymbolAddress((void**)&p_a1, g_a1);
    cudaGetSymbolAddress((void**)&p_a2, g_a2);
    cudaGetSymbolAddress((void**)&p_mu, g_mu);
    cudaGetSymbolAddress((void**)&p_cbT, g_cbT);
    cudaGetSymbolAddress((void**)&p_cnorm, g_cnorm);
    cudaGetSymbolAddress((void**)&p_xnorm, g_xnorm);

    // 0. codebook transpose + norms
    prep_codebook_kernel<<<KCB, 256>>>(codebook);

    // 1-3. VQ encoder
    sgemm_kernel<1><<<gemm_grid(BSZ, 512), 256>>>(Delta_X, enc_w1, enc_b1, nullptr, p_h1, BSZ, 512, 1024);
    sgemm_kernel<1><<<gemm_grid(BSZ, 1024), 256>>>(p_h1, enc_w2, enc_b2, nullptr, p_h2, BSZ, 1024, 512);
    sgemm_kernel<0><<<gemm_grid(BSZ, 1024), 256>>>(p_h2, prenet_w, prenet_b, nullptr, p_enc, BSZ, 1024, 1024);

    // 4-6. distances + argmin + gather
    rownorm_kernel<<<BSZ, 256>>>(p_enc, p_xnorm, OBS);
    sgemm_kernel<2><<<gemm_grid(BSZ, KCB), 256>>>(p_enc, p_cbT, p_cnorm, p_xnorm, p_dist, BSZ, KCB, OBS);
    argmin_kernel<<<BSZ, 256>>>(p_dist, out_prop);
    gather_kernel<<<(BSZ * OBS) / 256, 256>>>(codebook);

    // 7-10. postnet + decoder (forward st_q == quantized)
    sgemm_kernel<1><<<gemm_grid(BSZ, HENCD), 256>>>(p_quant, postnet_w, postnet_b, nullptr, p_d0, BSZ, HENCD, 1024);
    sgemm_kernel<1><<<gemm_grid(BSZ, 2048), 256>>>(p_d0, dec_w1, dec_b1, nullptr, p_d1, BSZ, 2048, 1024);
    sgemm_kernel<1><<<gemm_grid(BSZ, 2048), 256>>>(p_d1, dec_w2, dec_b2, nullptr, p_d2, BSZ, 2048, 2048);
    sgemm_kernel<0><<<gemm_grid(BSZ, 1024), 256>>>(p_d2, dec_w3, dec_b3, nullptr, p_recon, BSZ, 1024, 2048);

    // 11-14. actor
    concat_kernel<<<((size_t)BSZ * 1536) / 256, 256>>>(X);
    sgemm_kernel<1><<<gemm_grid(BSZ, 2048), 256>>>(p_cs, act_w1, act_b1, nullptr, p_a1, BSZ, 2048, 1536);
    sgemm_kernel<1><<<gemm_grid(BSZ, 2048), 256>>>(p_a1, act_w2, act_b2, nullptr, p_a2, BSZ, 2048, 2048);
    sgemm_kernel<0><<<gemm_grid(BSZ, 256), 256>>>(p_a2, act_w3, act_b3, nullptr, p_mu, BSZ, 256, 2048);

    // 15-17. losses
    loss_partial_kernel<<<2048, 256>>>(Delta_X);
    finalize_total_kernel<<<1, 256>>>(2048, out_total);
    policy_kernel<<<BSZ, 256>>>(A, log_std, out_loss, out_losspi);

    // 18. X pass-through
    cudaMemcpyAsync(out_X, X, (size_t)BSZ * OBS * sizeof(float),
                    cudaMemcpyDeviceToDevice);
}